// round 16
// baseline (speedup 1.0000x reference)
#include <cuda_runtime.h>

// ---------------- problem constants ----------------
#define NYD 256
#define NXD 256
#define PML 20
#define PADW 22            // PML + FD_PAD
#define NP  300            // padded grid edge
#define NT  250
#define NSHOT 2
#define NSRC 8
#define NREC 64
#define DTC 0.0005f

// strips
#define SSTR 60            // strips per shot
#define RROW 5             // rows per strip
#define NCTA (NSHOT * SSTR)   // 120 CTAs (<=148 SMs -> all resident, spin-sync safe)
#define BX 160             // one thread = one column PAIR (2*tid, 2*tid+1)
#define BY 5
#define NTHR (BX*BY)       // 800 threads, 25 warps
#define NWARP 25
#define NPX (NP + 8)       // 308: 4 guard columns each side, 8B-aligned pairs

// FD coefficients folded with 1/h and 1/h^2 (h = 5)
#define C1A ( 1.0f/60.0f)
#define C1B (-2.0f/15.0f)
#define C1C ( 2.0f/15.0f)
#define C1D (-1.0f/60.0f)
#define C2A (-1.0f/300.0f)
#define C2B ( 4.0f/75.0f)
#define C2C (-0.1f)

typedef unsigned long long u64;

// ---------------- persistent device state ----------------
__device__ float g_wf  [2][NSHOT][NP][NP];
__device__ float g_v2dt2[NP][NP];
__device__ float g_a[NP], g_b[NP];
__device__ int   g_sy[NSHOT*NSRC], g_sx[NSHOT*NSRC];
__device__ float g_sscale[NSHOT*NSRC];
__device__ int   g_ry[NSHOT*NREC], g_rx[NSHOT*NREC];
__device__ int   g_flag[NCTA * 32];          // per-CTA progress counters (25/step)

// ---------------- packed f32x2 ops on native u64 registers (no per-op MOVs) ----------------
__device__ __forceinline__ u64 pfma(u64 a, u64 b, u64 c) {
    u64 d; asm("fma.rn.f32x2 %0, %1, %2, %3;" : "=l"(d) : "l"(a), "l"(b), "l"(c)); return d;
}
__device__ __forceinline__ u64 pmul(u64 a, u64 b) {
    u64 d; asm("mul.rn.f32x2 %0, %1, %2;" : "=l"(d) : "l"(a), "l"(b)); return d;
}
__device__ __forceinline__ u64 padd(u64 a, u64 b) {
    u64 d; asm("add.rn.f32x2 %0, %1, %2;" : "=l"(d) : "l"(a), "l"(b)); return d;
}
__device__ __forceinline__ u64 pneg(u64 a) { return a ^ 0x8000000080000000ULL; }
__device__ __forceinline__ u64 pack2(float x, float y) {
    u64 d; asm("mov.b64 %0, {%1, %2};" : "=l"(d) : "f"(x), "f"(y)); return d;
}
__device__ __forceinline__ void unpack2(u64 v, float& x, float& y) {
    asm("mov.b64 {%0, %1}, %2;" : "=f"(x), "=f"(y) : "l"(v));
}
__device__ __forceinline__ u64 bcast(float s) { return pack2(s, s); }
// {hi(a), lo(b)}
__device__ __forceinline__ u64 shp(u64 a, u64 b) {
    u64 d;
    asm("{\n\t.reg .b32 al,ah,bl,bh;\n\t"
        "mov.b64 {al,ah}, %1;\n\tmov.b64 {bl,bh}, %2;\n\t"
        "mov.b64 %0, {ah,bl};\n\t}" : "=l"(d) : "l"(a), "l"(b));
    return d;
}
__device__ __forceinline__ u64 lds64(const float* p) { return *(const u64*)p; }
__device__ __forceinline__ void sts64(float* p, u64 v) { *(u64*)p = v; }
__device__ __forceinline__ u64 ldg64cg(const float* p) {
    u64 v; asm volatile("ld.global.cg.b64 %0, [%1];" : "=l"(v) : "l"(p)); return v;
}
__device__ __forceinline__ void stg64cg(float* p, u64 v) {
    asm volatile("st.global.cg.b64 [%0], %1;" :: "l"(p), "l"(v) : "memory");
}

// ---------------- scoped sync helpers ----------------
__device__ __forceinline__ int poll_flag(const int* p) {
    int v; asm volatile("ld.acquire.gpu.b32 %0, [%1];" : "=r"(v) : "l"(p)); return v;
}
__device__ __forceinline__ void red_release_add(int* p, int v) {
    asm volatile("red.release.gpu.global.add.u32 [%0], %1;" :: "l"(p), "r"(v) : "memory");
}

// ---------------- init kernel ----------------
__global__ void init_all(const float* __restrict__ v,
                         const int* __restrict__ sl, const int* __restrict__ rl)
{
    int idx = blockIdx.x * blockDim.x + threadIdx.x;
    int stride = gridDim.x * blockDim.x;

    float* wf = &g_wf[0][0][0][0];
    const int NSTATE = 2 * NSHOT * NP * NP;
    for (int i = idx; i < NSTATE; i += stride) wf[i] = 0.f;

    for (int i = idx; i < NP * NP; i += stride) {
        int y = i / NP, x = i - y * NP;
        int vy = min(max(y - PADW, 0), NYD - 1);
        int vx = min(max(x - PADW, 0), NXD - 1);
        float vv = v[vy * NXD + vx];
        (&g_v2dt2[0][0])[i] = vv * vv * (DTC * DTC);
    }

    for (int i = idx; i < NP; i += stride) {
        double fi = (double)i;
        double frac = fmax(22.0 - fi, fi - 277.0) / (double)PML;
        frac = fmin(fmax(frac, 0.0), 1.0);
        double sm   = 3.0 * 4000.0 * log(1000.0) / (2.0 * PML * 5.0);
        double sig  = sm * frac * frac;
        double alp  = 3.141592653589793 * 25.0 * (1.0 - frac);
        double bb   = exp(-(sig + alp) * (double)DTC);
        double aa   = sig / (sig + alp + 1e-9) * (bb - 1.0);
        g_a[i] = (float)aa;
        g_b[i] = (float)bb;
    }

    for (int i = idx; i < NCTA * 32; i += stride) g_flag[i] = 0;

    if (idx == 0) {
        bool s64 = true;
        for (int k = 1; k < NSHOT * NSRC * 2; k += 2) if (sl[k] != 0) { s64 = false; break; }
        for (int s = 0; s < NSHOT * NSRC; s++) {
            int y = s64 ? sl[4*s]     : sl[2*s];
            int x = s64 ? sl[4*s + 2] : sl[2*s + 1];
            g_sy[s] = y + PADW; g_sx[s] = x + PADW;
            float vv = v[y * NXD + x];
            g_sscale[s] = vv * vv * (DTC * DTC);
        }
        bool r64 = true;
        for (int k = 1; k < NSHOT * NREC * 2; k += 2) if (rl[k] != 0) { r64 = false; break; }
        for (int s = 0; s < NSHOT * NREC; s++) {
            int y = r64 ? rl[4*s]     : rl[2*s];
            int x = r64 ? rl[4*s + 2] : rl[2*s + 1];
            g_ry[s] = y + PADW; g_rx[s] = x + PADW;
        }
    }
}

// ---------------- persistent wave kernel ----------------
// R15 skeleton; all packed math on native u64 registers.
__global__ void __launch_bounds__(NTHR, 1)
wave_kernel(const float* __restrict__ amp, float* __restrict__ out)
{
    const int bid   = blockIdx.x;
    const int shot  = bid / SSTR;
    const int strip = bid - shot * SSTR;
    const int y0    = strip * RROW;
    const int tid   = threadIdx.x;
    const int r     = threadIdx.y;
    const int tidl  = threadIdx.x + BX * threadIdx.y;
    const int c0    = 2 * tid;
    const bool act  = (c0 < NP);
    const int cc    = c0 + 4;

    __shared__ float s_w[2][13][NPX];        // double-buffered wf rows y0-4 .. y0+8
    __shared__ float s_axp[NPX], s_bxp[NPX]; // x profiles (guard-padded)
    __shared__ u64  s_aA2[9], s_bA2[9];      // y profiles, pre-duplicated pairs
    __shared__ int   s_nsrc, s_nrec;
    __shared__ int   s_src_r[NSRC], s_src_c[NSRC], s_src_idx[NSRC];
    __shared__ float s_src_scale[NSRC];
    __shared__ short s_rec_r[NREC], s_rec_c[NREC];
    __shared__ int   s_rec_out[NREC];

    // zero guard columns in BOTH buffers (cols 0..3 and NP+4..NP+7)
    if (tidl < 26) {
        int b = tidl / 13, row = tidl % 13;
        #pragma unroll
        for (int g = 0; g < 4; g++) {
            s_w[b][row][g] = 0.f;
            s_w[b][row][NP + 4 + g] = 0.f;
        }
    }
    for (int i = tidl; i < NPX; i += NTHR) {
        int col = i - 4;
        bool in = (col >= 0 && col < NP);
        s_axp[i] = in ? g_a[col] : 0.f;
        s_bxp[i] = in ? g_b[col] : 0.f;
    }
    if (tidl >= 32 && tidl < 41) {
        int j = tidl - 32;
        int y = y0 - 2 + j;
        bool in = (y >= 0 && y < NP);
        float a = in ? g_a[y] : 0.f;
        float b = in ? g_b[y] : 0.f;
        s_aA2[j] = pack2(a, a);
        s_bA2[j] = pack2(b, b);
    }
    if (tidl == 0) {
        int ns = 0;
        for (int i = 0; i < NSRC; i++) {
            int s = shot * NSRC + i;
            int rr = g_sy[s] - y0;
            if (rr >= 0 && rr < RROW) {
                s_src_r[ns] = rr; s_src_c[ns] = g_sx[s];
                s_src_idx[ns] = s; s_src_scale[ns] = g_sscale[s]; ns++;
            }
        }
        s_nsrc = ns;
        int nr = 0;
        for (int i = 0; i < NREC; i++) {
            int s = shot * NREC + i;
            int rr = g_ry[s] - y0;
            if (rr >= 0 && rr < RROW) {
                s_rec_r[nr] = (short)rr; s_rec_c[nr] = (short)g_rx[s];
                s_rec_out[nr] = s * NT; nr++;
            }
        }
        s_nrec = nr;
    }

    // prologue: own rows of buffer 0 start at zero
    if (act) sts64(&s_w[0][4 + r][cc], 0ULL);

    // ---- per-thread register state (all packed u64) ----
    u64 wc = 0, wm = 0, zy = 0, zx = 0;
    u64 pyr0 = 0, pyr1 = 0, pyr2 = 0, pyr3 = 0, pyr4 = 0;
    u64 pxL = 0, pxM = 0, pxR = 0;
    u64 v2 = 0, axM = 0, bxM = 0;
    if (act) {
        v2  = lds64(0 ? 0 : &g_v2dt2[y0 + r][c0]);   // 8B-aligned (c0 even)
        axM = pack2(g_a[c0], g_a[c0 + 1]);
        bxM = pack2(g_b[c0], g_b[c0 + 1]);
    }
    const u64 kC1A = bcast(C1A), kC1B = bcast(C1B), kC1C = bcast(C1C), kC1D = bcast(C1D);
    const u64 kC2A = bcast(C2A), kC2B = bcast(C2B), kC2C = bcast(C2C);

    const float* wfb[2] = { &g_wf[0][shot][0][0], &g_wf[1][shot][0][0] };
    __syncthreads();   // tables + prologue ready

    // hoisted x-profile neighbor pairs (constant over time; 8B-aligned)
    u64 axL = 0, bxL = 0, axR = 0, bxR = 0;
    if (act) {
        axL = lds64(&s_axp[cc - 2]); bxL = lds64(&s_bxp[cc - 2]);
        axR = lds64(&s_axp[cc + 2]); bxR = lds64(&s_bxp[cc + 2]);
    }

    // ---- static per-thread source mapping ----
    int sk0 = -1, sk1 = -1, sg0 = 0, sg1 = 0, so0 = 0, so1 = 0;
    float ss0 = 0.f, ss1 = 0.f;
    {
        const int ns = s_nsrc;
        for (int i = 0; i < ns; i++) {
            if (s_src_r[i] == r && (s_src_c[i] >> 1) == tid) {
                if (sk0 < 0) { sk0 = i; sg0 = s_src_idx[i]; so0 = s_src_c[i] & 1; ss0 = s_src_scale[i]; }
                else         { sk1 = i; sg1 = s_src_idx[i]; so1 = s_src_c[i] & 1; ss1 = s_src_scale[i]; }
            }
        }
    }
    // ---- static per-thread receiver mapping ----
    int rq0 = -1, rq1 = -1, rb0 = 0, rb1 = 0, ro0 = 0, ro1 = 0;
    {
        const int nr = s_nrec;
        for (int i = 0; i < nr; i++) {
            if (s_rec_r[i] == r && (s_rec_c[i] >> 1) == tid) {
                if (rq0 < 0) { rq0 = i; rb0 = s_rec_out[i]; ro0 = s_rec_c[i] & 1; }
                else         { rq1 = i; rb1 = s_rec_out[i]; ro1 = s_rec_c[i] & 1; }
            }
        }
    }

    int* const myflag = &g_flag[bid * 32];
    const int* upflag = (strip > 0)        ? &g_flag[(bid - 1) * 32] : nullptr;
    const int* dnflag = (strip < SSTR - 1) ? &g_flag[(bid + 1) * 32] : nullptr;
    int thr = 0;

    for (int t = 0; t < NT; t++) {
        const int p = t & 1;
        const float* __restrict__ wfcg = wfb[p];
        float* __restrict__ wfn        = (float*)wfb[1 - p];
        float (* __restrict__ sw)[NPX] = s_w[p];

        // ---- staging: per-thread acquire polls precede this thread's halo LDGs ----
        if (act) {
            if (r <= 1) {
                if (upflag) { while (poll_flag(upflag) < thr) { } }
                #pragma unroll
                for (int k = 0; k < 2; k++) {
                    int wrow = r * 2 + k;              // 0..3
                    int y = y0 - 4 + wrow;
                    u64 hv = (y >= 0) ? ldg64cg(&wfcg[y * NP + c0]) : 0ULL;
                    sts64(&sw[wrow][cc], hv);
                }
            } else if (r <= 3) {
                if (dnflag) { while (poll_flag(dnflag) < thr) { } }
                #pragma unroll
                for (int k = 0; k < 2; k++) {
                    int wrow = 9 + (r - 2) * 2 + k;    // 9..12
                    int y = y0 - 4 + wrow;
                    u64 hv = (y < NP) ? ldg64cg(&wfcg[y * NP + c0]) : 0ULL;
                    sts64(&sw[wrow][cc], hv);
                }
            }
        }

        // source amp prefetch (overlaps staging/barrier)
        float a0 = 0.f, a1 = 0.f;
        if (sk0 >= 0) a0 = __ldcg(&amp[sg0 * NT + t]);
        if (sk1 >= 0) a1 = __ldcg(&amp[sg1 * NT + t]);

        __syncthreads();

        // ---- fused compute, fully packed ----
        if (act) {
            u64 w0 = lds64(&sw[r + 0][cc]);
            u64 w1 = lds64(&sw[r + 1][cc]);
            u64 w2 = lds64(&sw[r + 2][cc]);
            u64 w3 = lds64(&sw[r + 3][cc]);
            u64 w4 = wc;
            u64 w5 = lds64(&sw[r + 5][cc]);
            u64 w6 = lds64(&sw[r + 6][cc]);
            u64 w7 = lds64(&sw[r + 7][cc]);
            u64 w8 = lds64(&sw[r + 8][cc]);

            // psi_y recursion at 5 rows (profile pairs via single LDS.64)
            {
                u64 d;
                d = pfma(kC1A, w0, pfma(kC1B, w1, pfma(kC1C, w3, pmul(kC1D, w4))));
                pyr0 = pfma(s_bA2[r + 0], pyr0, pmul(s_aA2[r + 0], d));
                d = pfma(kC1A, w1, pfma(kC1B, w2, pfma(kC1C, w4, pmul(kC1D, w5))));
                pyr1 = pfma(s_bA2[r + 1], pyr1, pmul(s_aA2[r + 1], d));
                d = pfma(kC1A, w2, pfma(kC1B, w3, pfma(kC1C, w5, pmul(kC1D, w6))));
                pyr2 = pfma(s_bA2[r + 2], pyr2, pmul(s_aA2[r + 2], d));
                d = pfma(kC1A, w3, pfma(kC1B, w4, pfma(kC1C, w6, pmul(kC1D, w7))));
                pyr3 = pfma(s_bA2[r + 3], pyr3, pmul(s_aA2[r + 3], d));
                d = pfma(kC1A, w4, pfma(kC1B, w5, pfma(kC1C, w7, pmul(kC1D, w8))));
                pyr4 = pfma(s_bA2[r + 4], pyr4, pmul(s_aA2[r + 4], d));
            }

            u64 XL2 = lds64(&sw[r + 4][cc - 4]);
            u64 XL  = lds64(&sw[r + 4][cc - 2]);
            u64 XM  = w4;
            u64 XR  = lds64(&sw[r + 4][cc + 2]);
            u64 XR2 = lds64(&sw[r + 4][cc + 4]);
            u64 s1 = shp(XL2, XL), s2 = shp(XL, XM), s3 = shp(XM, XR), s4 = shp(XR, XR2);

            // psi_x recursion at 3 column pairs
            {
                u64 d;
                d = pfma(kC1A, XL2, pfma(kC1B, s1, pfma(kC1C, s2, pmul(kC1D, XM))));
                pxL = pfma(bxL, pxL, pmul(axL, d));
                d = pfma(kC1A, XL, pfma(kC1B, s2, pfma(kC1C, s3, pmul(kC1D, XR))));
                pxM = pfma(bxM, pxM, pmul(axM, d));
                d = pfma(kC1A, XM, pfma(kC1B, s3, pfma(kC1C, s4, pmul(kC1D, XR2))));
                pxR = pfma(bxR, pxR, pmul(axR, d));
            }

            u64 d2y = pfma(kC2A, w2, pfma(kC2B, w3, pfma(kC2C, w4,
                      pfma(kC2B, w5, pmul(kC2A, w6)))));
            u64 d2x = pfma(kC2A, XL, pfma(kC2B, s2, pfma(kC2C, XM,
                      pfma(kC2B, s3, pmul(kC2A, XR)))));
            u64 dpy = pfma(kC1A, pyr0, pfma(kC1B, pyr1,
                      pfma(kC1C, pyr3, pmul(kC1D, pyr4))));
            u64 dpx = pfma(kC1A, pxL, pfma(kC1B, shp(pxL, pxM),
                      pfma(kC1C, shp(pxM, pxR), pmul(kC1D, pxR))));

            u64 syv = padd(d2y, dpy);
            u64 sxv = padd(d2x, dpx);
            u64 nzy = pfma(s_bA2[r + 2], zy, pmul(s_aA2[r + 2], syv));
            u64 nzx = pfma(bxM, zx, pmul(axM, sxv));
            zy = nzy; zx = nzx;
            u64 lap  = padd(padd(padd(syv, sxv), nzy), nzx);
            u64 base = padd(padd(wc, wc), pneg(wm));      // 2*wc - wm
            u64 wp   = pfma(v2, lap, base);

            if (sk0 >= 0 || sk1 >= 0) {
                float wx, wy; unpack2(wp, wx, wy);
                if (sk0 >= 0) { float add = ss0 * a0; if (so0) wy += add; else wx += add; }
                if (sk1 >= 0) { float add = ss1 * a1; if (so1) wy += add; else wx += add; }
                wp = pack2(wx, wy);
            }

            stg64cg(&wfn[(y0 + r) * NP + c0], wp);       // for neighbors
            sts64(&s_w[1 - p][4 + r][cc], wp);           // for own CTA next step
            wm = wc; wc = wp;
        }

        // ---- per-warp release ----
        __syncwarp();
        if ((tidl & 31) == 0) red_release_add(myflag, 1);

        // receiver write-out (off critical path, after release)
        if (rq0 >= 0 || rq1 >= 0) {
            float wx, wy; unpack2(wc, wx, wy);
            if (rq0 >= 0) out[rb0 + t] = ro0 ? wy : wx;
            if (rq1 >= 0) out[rb1 + t] = ro1 ? wy : wx;
        }

        thr += NWARP;
    }
}

// ---------------- launch ----------------
extern "C" void kernel_launch(void* const* d_in, const int* in_sizes, int n_in,
                              void* d_out, int out_size)
{
    const float* v   = (const float*)d_in[0];
    const float* amp = (const float*)d_in[1];
    const int*   sl  = (const int*)d_in[2];
    const int*   rl  = (const int*)d_in[3];

    init_all<<<NCTA, 256>>>(v, sl, rl);
    dim3 blk(BX, BY);
    wave_kernel<<<NCTA, blk>>>(amp, (float*)d_out);
}